// round 12
// baseline (speedup 1.0000x reference)
#include <cuda_runtime.h>
#include <cstdint>
#include <cstddef>

typedef unsigned long long u64;

// ---- packed f32x2 helpers (Blackwell sm_103a) ----
#define FMA2(d, a, b, c) asm("fma.rn.f32x2 %0, %1, %2, %3;" : "=l"(d) : "l"(a), "l"(b), "l"(c))
#define MUL2(d, a, b)    asm("mul.rn.f32x2 %0, %1, %2;"     : "=l"(d) : "l"(a), "l"(b))
#define ADD2(d, a, b)    asm("add.rn.f32x2 %0, %1, %2;"     : "=l"(d) : "l"(a), "l"(b))

__device__ __forceinline__ u64 pack2(float lo, float hi) {
    u64 r; asm("mov.b64 %0, {%1, %2};" : "=l"(r) : "f"(lo), "f"(hi)); return r;
}
__device__ __forceinline__ float2 unpack2(u64 v) {
    float2 r; asm("mov.b64 {%0, %1}, %2;" : "=f"(r.x), "=f"(r.y) : "l"(v)); return r;
}
__device__ __forceinline__ void stg_cs_v4(float* p, float4 v) {
    asm volatile("st.global.cs.v4.f32 [%0], {%1, %2, %3, %4};"
                 :: "l"(p), "f"(v.x), "f"(v.y), "f"(v.z), "f"(v.w) : "memory");
}
__device__ __forceinline__ uint32_t smem_u32(const void* p) {
    uint32_t a;
    asm("{ .reg .u64 t; cvta.to.shared.u64 t, %1; cvt.u32.u64 %0, t; }" : "=r"(a) : "l"(p));
    return a;
}
__device__ __forceinline__ void mbar_init(uint32_t mbar, uint32_t cnt) {
    asm volatile("mbarrier.init.shared.b64 [%0], %1;" :: "r"(mbar), "r"(cnt) : "memory");
}
__device__ __forceinline__ void mbar_expect_tx(uint32_t mbar, uint32_t bytes) {
    asm volatile("mbarrier.arrive.expect_tx.shared.b64 _, [%0], %1;" :: "r"(mbar), "r"(bytes) : "memory");
}
__device__ __forceinline__ void bulk_g2s(uint32_t dst, const void* src, uint32_t bytes, uint32_t mbar) {
    asm volatile("cp.async.bulk.shared::cta.global.mbarrier::complete_tx::bytes [%0], [%1], %2, [%3];"
                 :: "r"(dst), "l"(src), "r"(bytes), "r"(mbar) : "memory");
}
__device__ __forceinline__ void mbar_wait(uint32_t mbar, uint32_t parity) {
    asm volatile(
        "{\n\t"
        ".reg .pred P1;\n\t"
        "WL_%=:\n\t"
        "mbarrier.try_wait.parity.acquire.cta.shared::cta.b64 P1, [%0], %1, 0x989680;\n\t"
        "@P1 bra.uni WD_%=;\n\t"
        "bra.uni WL_%=;\n\t"
        "WD_%=:\n\t"
        "}"
        :: "r"(mbar), "r"(parity) : "memory");
}

constexpr int E_DIM = 1024;

// ============================================================================
// Fused: h = x@w1^T + b1 ; q = Pauli-Z cosine strings ; out = q@w2^T + b2
//   q0=c0, q1=c1, q2=c0c2, q3=c1c3, q4=c0c2c4, q5=c1c3c5, q6=c0c2c4c6,
//   q7=c0..c7  with c_i = cos(h_i)
//
// R11 structure + NSLOT 2->3 (48KB TMA ring): per-CTA outstanding reads grow
// 32->48KB. The chip needs ~27KB in flight per CTA to sustain its HBM share
// (8TB/s / 592 CTAs at ~2us loaded TMA latency); 2 slots was marginal.
// Ring overflows the 48KB static-smem limit -> dynamic smem (57.4KB/CTA,
// still 4 CTAs/SM), with s_q aliased into s_part (extra sync fence).
// ============================================================================
constexpr int RPB     = 32;                  // rows per block
constexpr int SROWS   = 4;                   // rows per pipeline stage
constexpr int NSLOT   = 3;                   // ring depth
constexpr int NSTAGE  = RPB / SROWS;         // 8
constexpr int STBYTES = SROWS * E_DIM * 4;   // 16384

// dynamic smem layout (bytes)
constexpr int OFF_XS    = 0;                         // ring: 3 * 16384 = 49152
constexpr int OFF_PART  = OFF_XS + NSLOT * STBYTES;  // s_part: 32*8*8*4 = 8192
constexpr int OFF_MBAR  = OFF_PART + RPB * 8 * 8 * 4;
constexpr int SMEM_TOTAL= OFF_MBAR + NSLOT * 8;      // 57368

__global__ void __launch_bounds__(256, 4)
ffq_fused(const float* __restrict__ x,  const float* __restrict__ w1,
          const float* __restrict__ b1, const float* __restrict__ w2,
          const float* __restrict__ b2, float* __restrict__ out, int rows)
{
    extern __shared__ __align__(128) char dsm[];
    float* xs     = reinterpret_cast<float*>(dsm + OFF_XS);     // [NSLOT][4096]
    float* s_part = reinterpret_cast<float*>(dsm + OFF_PART);   // [32][8][8]
    float* s_q    = s_part;                                     // aliased (1KB)

    const int tid  = threadIdx.x;
    const int warp = tid >> 5;
    const int lane = tid & 31;

    const uint32_t mb0 = smem_u32(dsm + OFF_MBAR);
    const uint32_t xs0 = smem_u32(xs);

    // ---- [A] phase-1 weights: f-pair packed, warp owns 128-wide e-slice ----
    const int e1 = warp * 128 + lane * 4;
    u64 wpk[4][4];
#pragma unroll
    for (int p = 0; p < 4; p++) {
        const float* w0 = w1 + (2 * p)     * E_DIM + e1;
        const float* w1r= w1 + (2 * p + 1) * E_DIM + e1;
#pragma unroll
        for (int e = 0; e < 4; e++)
            wpk[p][e] = pack2(w0[e], w1r[e]);
    }
    const float bf = b1[tid & 7];

    if (tid == 0) {
#pragma unroll
        for (int k = 0; k < NSLOT; k++) mbar_init(mb0 + k * 8, 1);
    }
    __syncthreads();

    const int    block_row0 = blockIdx.x * RPB;
    const float* src = x + (size_t)block_row0 * E_DIM;

    // prime all ring slots
    if (tid == 0) {
#pragma unroll
        for (int k = 0; k < NSLOT; k++) {
            mbar_expect_tx(mb0 + k * 8, STBYTES);
            bulk_g2s(xs0 + k * STBYTES, src + (size_t)k * SROWS * E_DIM,
                     STBYTES, mb0 + k * 8);
        }
    }

    const bool hi16 = (lane & 16);
    const bool hi8  = (lane & 8);

    for (int s = 0; s < NSTAGE; s++) {
        const int slot = s % NSLOT;
        mbar_wait(mb0 + slot * 8, (s / NSLOT) & 1);

        const float* xslot = xs + slot * (SROWS * E_DIM);

#pragma unroll
        for (int r = 0; r < SROWS; r++) {
            float4 xv = *reinterpret_cast<const float4*>(
                xslot + r * E_DIM + e1);
            u64 xd[4];
            xd[0] = pack2(xv.x, xv.x);
            xd[1] = pack2(xv.y, xv.y);
            xd[2] = pack2(xv.z, xv.z);
            xd[3] = pack2(xv.w, xv.w);

            u64 v0, v1, v2, v3;
            MUL2(v0, xd[0], wpk[0][0]);
            MUL2(v1, xd[0], wpk[1][0]);
            MUL2(v2, xd[0], wpk[2][0]);
            MUL2(v3, xd[0], wpk[3][0]);
#pragma unroll
            for (int e = 1; e < 4; e++) {
                FMA2(v0, xd[e], wpk[0][e], v0);
                FMA2(v1, xd[e], wpk[1][e], v1);
                FMA2(v2, xd[e], wpk[2][e], v2);
                FMA2(v3, xd[e], wpk[3][e], v3);
            }

            // packed value-halving butterfly on 4 u64 pair-accumulators
            {
                u64 s0 = hi16 ? v0 : v2;
                u64 s1 = hi16 ? v1 : v3;
                u64 k0 = hi16 ? v2 : v0;
                u64 k1 = hi16 ? v3 : v1;
                u64 r0 = __shfl_xor_sync(0xffffffffu, s0, 16);
                u64 r1 = __shfl_xor_sync(0xffffffffu, s1, 16);
                ADD2(v0, k0, r0);
                ADD2(v1, k1, r1);
            }
            u64 w;
            {
                u64 sv = hi8 ? v0 : v1;
                u64 kv = hi8 ? v1 : v0;
                u64 rv = __shfl_xor_sync(0xffffffffu, sv, 8);
                ADD2(w, kv, rv);
            }
            {
                u64 rv = __shfl_xor_sync(0xffffffffu, w, 4);
                ADD2(w, w, rv);
                rv = __shfl_xor_sync(0xffffffffu, w, 2);
                ADD2(w, w, rv);
                rv = __shfl_xor_sync(0xffffffffu, w, 1);
                ADD2(w, w, rv);
            }
            if ((lane & 7) == 0) {
                const int p = lane >> 3;
                // s_part[row][warp][f] layout, row = s*SROWS + r
                *reinterpret_cast<u64*>(
                    s_part + ((s * SROWS + r) * 8 + warp) * 8 + 2 * p) = w;
            }
        }
        __syncthreads();   // slot drained; s_part row-group committed

        if (tid == 0 && s + NSLOT < NSTAGE) {
            mbar_expect_tx(mb0 + slot * 8, STBYTES);
            bulk_g2s(xs0 + slot * STBYTES,
                     src + (size_t)(s + NSLOT) * SROWS * E_DIM,
                     STBYTES, mb0 + slot * 8);
        }
    }

    // ---- [B] q epilogue: 32 rows x 8 f = 256 items, 1 per thread ----
    float qv;
    {
        const int r  = tid >> 3;          // 0..31
        const int ff = tid & 7;           // matches bf

        float h = bf;
#pragma unroll
        for (int w = 0; w < 8; w++) h += s_part[(r * 8 + w) * 8 + ff];
        float c = __cosf(h);

        const int base = lane & 24;
        float cs[8];
#pragma unroll
        for (int jj = 0; jj < 8; jj++)
            cs[jj] = __shfl_sync(0xffffffffu, c, base + jj);

        if (ff == 7) {
            qv = cs[0]*cs[1]*cs[2]*cs[3]*cs[4]*cs[5]*cs[6]*cs[7];
        } else {
            qv = 1.0f;
#pragma unroll
            for (int jj = 0; jj < 8; jj++)
                if (jj <= ff && ((jj ^ ff) & 1) == 0) qv *= cs[jj];
        }
    }
    __syncthreads();       // all s_part reads done before aliased q store
    s_q[tid] = qv;         // s_q[r][ff] with r=tid>>3, ff=tid&7
    __syncthreads();

    // ---- [C] out tail: w2 f-pairs in regs (loaded after w1 regs die) ----
    const int e2 = tid * 4;
    u64 wp[4][4];
#pragma unroll
    for (int i = 0; i < 4; i++) {
        ulonglong2 v0 = *reinterpret_cast<const ulonglong2*>(w2 + (e2 + i) * 8);
        ulonglong2 v1 = *reinterpret_cast<const ulonglong2*>(w2 + (e2 + i) * 8 + 4);
        wp[i][0] = v0.x; wp[i][1] = v0.y;
        wp[i][2] = v1.x; wp[i][3] = v1.y;
    }
    u64 binit[4];
    {
        float4 bv = *reinterpret_cast<const float4*>(b2 + e2);
        binit[0] = pack2(bv.x, 0.f);
        binit[1] = pack2(bv.y, 0.f);
        binit[2] = pack2(bv.z, 0.f);
        binit[3] = pack2(bv.w, 0.f);
    }

    float* orow = out + (size_t)block_row0 * E_DIM + e2;
#pragma unroll 8
    for (int r = 0; r < RPB; r++) {
        ulonglong2 qv0 = *reinterpret_cast<const ulonglong2*>(s_q + r * 8);
        ulonglong2 qv1 = *reinterpret_cast<const ulonglong2*>(s_q + r * 8 + 4);

        float o[4];
#pragma unroll
        for (int i = 0; i < 4; i++) {
            u64 acc = binit[i];
            FMA2(acc, qv0.x, wp[i][0], acc);
            FMA2(acc, qv0.y, wp[i][1], acc);
            FMA2(acc, qv1.x, wp[i][2], acc);
            FMA2(acc, qv1.y, wp[i][3], acc);
            float2 t = unpack2(acc);
            o[i] = t.x + t.y;
        }
        stg_cs_v4(orow, make_float4(o[0], o[1], o[2], o[3]));
        orow += E_DIM;
    }
}

extern "C" void kernel_launch(void* const* d_in, const int* in_sizes, int n_in,
                              void* d_out, int out_size) {
    const float* x  = (const float*)d_in[0];
    const float* w1 = (const float*)d_in[1];
    const float* b1 = (const float*)d_in[2];
    const float* w2 = (const float*)d_in[3];
    const float* b2 = (const float*)d_in[4];
    float* out = (float*)d_out;

    // dynamic smem > 48KB needs an explicit opt-in (idempotent, host-side)
    cudaFuncSetAttribute(ffq_fused, cudaFuncAttributeMaxDynamicSharedMemorySize,
                         SMEM_TOTAL);

    const int rows = in_sizes[0] / E_DIM;        // 32768
    ffq_fused<<<rows / RPB, 256, SMEM_TOTAL>>>(x, w1, b1, w2, b2, out, rows);
}